// round 16
// baseline (speedup 1.0000x reference)
#include <cuda_runtime.h>
#include <cuda_bf16.h>
#include <cstdint>

// Problem constants
#define BATCH 4
#define TSEQ  2048
#define CDIM  1024
#define NHEAD 16
#define HD    64
#define MROWS (BATCH * TSEQ)   // 8192

// Arch feature gate: tcgen05 only exists on the 'a' targets.
#if defined(__CUDA_ARCH_FEAT_SM103_ALL) || defined(__CUDA_ARCH_FEAT_SM100_ALL) || defined(__CUDA_ARCH_FEAT_SM101_ALL)
#define HAS_TCGEN05 1
#else
#define HAS_TCGEN05 0
#endif

// Scratch (device globals; no allocations allowed)
__device__ unsigned g_xt [(size_t)MROWS * CDIM];        // x, tf32, k-permuted
__device__ unsigned g_wat[(size_t)3 * CDIM * CDIM];     // w_attn, tf32, k-permuted
__device__ unsigned g_wpt[(size_t)CDIM * CDIM];         // w_proj, tf32, k-permuted
__device__ unsigned g_qkv[(size_t)MROWS * 3 * CDIM];    // q,k tf32 bits natural
__device__ unsigned g_vt [(size_t)BATCH * NHEAD * HD * TSEQ]; // V^T tf32 bits [b,h,d,t]
__device__ unsigned g_yt [(size_t)MROWS * CDIM];        // y, tf32 bits, k-permuted

// ---------------------------------------------------------------------------
// generic helpers
// ---------------------------------------------------------------------------
__device__ __forceinline__ unsigned f2tf32(float f) {
    unsigned u;
    asm("cvt.rna.tf32.f32 %0, %1;" : "=r"(u) : "f"(f));
    return u;
}

__device__ __forceinline__ void mma_tf32(float c[4],
                                         unsigned a0, unsigned a1, unsigned a2, unsigned a3,
                                         unsigned b0, unsigned b1)
{
    asm volatile(
        "mma.sync.aligned.m16n8k8.row.col.f32.tf32.tf32.f32 "
        "{%0,%1,%2,%3}, {%4,%5,%6,%7}, {%8,%9}, {%0,%1,%2,%3};"
        : "+f"(c[0]), "+f"(c[1]), "+f"(c[2]), "+f"(c[3])
        : "r"(a0), "r"(a1), "r"(a2), "r"(a3), "r"(b0), "r"(b1));
}

__device__ __forceinline__ void cp_async16(uint32_t saddr, const void* gptr) {
    asm volatile("cp.async.cg.shared.global [%0], [%1], 16;" :: "r"(saddr), "l"(gptr));
}
__device__ __forceinline__ void cp_commit() {
    asm volatile("cp.async.commit_group;");
}
template<int N_>
__device__ __forceinline__ void cp_wait() {
    asm volatile("cp.async.wait_group %0;" :: "n"(N_));
}

__device__ __forceinline__ uint32_t elect_one() {
    uint32_t pred;
    asm volatile("{\n\t.reg .pred p;\n\telect.sync _|p, 0xFFFFFFFF;\n\t"
                 "selp.b32 %0, 1, 0, p;\n\t}" : "=r"(pred));
    return pred;
}

// k-permutation within 16-word groups (HMMA fragment pairing; dot-product invariant)
__device__ __host__ __forceinline__ int perm16(int i) {
    int lo = i & 7;
    return ((i >> 3) << 3) | ((lo & 3) << 1) | (lo >> 2);
}

// ---------------------------------------------------------------------------
// mbarrier helpers (valid on all targets)
// ---------------------------------------------------------------------------
#define MBAR_INIT(addr, cnt) \
    asm volatile("mbarrier.init.shared.b64 [%0], %1;" :: "r"(addr), "r"(cnt) : "memory")

#define MBAR_WAIT(addr, phase) do {                                             \
    asm volatile(                                                               \
        "{\n\t.reg .pred P1;\n\t"                                               \
        "WAIT_%=:\n\t"                                                          \
        "mbarrier.try_wait.parity.acquire.cta.shared::cta.b64 P1, [%0], %1, 0x989680;\n\t" \
        "@P1 bra.uni DONE_%=;\n\t"                                              \
        "bra.uni WAIT_%=;\n\t"                                                  \
        "DONE_%=:\n\t}"                                                         \
        :: "r"(addr), "r"(phase) : "memory");                                   \
} while (0)

// ---------------------------------------------------------------------------
// tcgen05 helpers — only instantiated under HAS_TCGEN05
// ---------------------------------------------------------------------------
#if HAS_TCGEN05
#define TC_ALLOC(slot, n) \
    asm volatile("tcgen05.alloc.cta_group::1.sync.aligned.shared::cta.b32 [%0], %1;" \
                 :: "r"(slot), "r"(n) : "memory")
#define TC_RELINQ() \
    asm volatile("tcgen05.relinquish_alloc_permit.cta_group::1.sync.aligned;")
#define TC_DEALLOC(base, n) \
    asm volatile("tcgen05.dealloc.cta_group::1.sync.aligned.b32 %0, %1;" :: "r"(base), "r"(n))
#define TC_COMMIT(mbar) \
    asm volatile("tcgen05.commit.cta_group::1.mbarrier::arrive::one.shared::cluster.b64 [%0];" \
                 :: "r"(mbar) : "memory")
#define TC_FENCE_AFTER()   asm volatile("tcgen05.fence::after_thread_sync;" ::: "memory")
#define TC_FENCE_BEFORE()  asm volatile("tcgen05.fence::before_thread_sync;" ::: "memory")
#define TC_WAIT_LD()       asm volatile("tcgen05.wait::ld.sync.aligned;" ::: "memory")
#define TC_WAIT_ST()       asm volatile("tcgen05.wait::st.sync.aligned;" ::: "memory")
#define FENCE_PROXY()      asm volatile("fence.proxy.async.shared::cta;" ::: "memory")

#define TC_LD_X32(r, addr) \
    asm volatile( \
        "tcgen05.ld.sync.aligned.32x32b.x32.b32 " \
        "{%0, %1, %2, %3, %4, %5, %6, %7, " \
        " %8, %9, %10, %11, %12, %13, %14, %15, " \
        " %16, %17, %18, %19, %20, %21, %22, %23, " \
        " %24, %25, %26, %27, %28, %29, %30, %31}, [%32];" \
        : "=r"((r)[0]),  "=r"((r)[1]),  "=r"((r)[2]),  "=r"((r)[3]), \
          "=r"((r)[4]),  "=r"((r)[5]),  "=r"((r)[6]),  "=r"((r)[7]), \
          "=r"((r)[8]),  "=r"((r)[9]),  "=r"((r)[10]), "=r"((r)[11]), \
          "=r"((r)[12]), "=r"((r)[13]), "=r"((r)[14]), "=r"((r)[15]), \
          "=r"((r)[16]), "=r"((r)[17]), "=r"((r)[18]), "=r"((r)[19]), \
          "=r"((r)[20]), "=r"((r)[21]), "=r"((r)[22]), "=r"((r)[23]), \
          "=r"((r)[24]), "=r"((r)[25]), "=r"((r)[26]), "=r"((r)[27]), \
          "=r"((r)[28]), "=r"((r)[29]), "=r"((r)[30]), "=r"((r)[31]) \
        : "r"(addr))

#define TC_ST_X32(addr, r) \
    asm volatile( \
        "tcgen05.st.sync.aligned.32x32b.x32.b32 [%0], " \
        "{%1, %2, %3, %4, %5, %6, %7, %8, " \
        " %9, %10, %11, %12, %13, %14, %15, %16, " \
        " %17, %18, %19, %20, %21, %22, %23, %24, " \
        " %25, %26, %27, %28, %29, %30, %31, %32};" \
        :: "r"(addr), \
           "r"((r)[0]),  "r"((r)[1]),  "r"((r)[2]),  "r"((r)[3]), \
           "r"((r)[4]),  "r"((r)[5]),  "r"((r)[6]),  "r"((r)[7]), \
           "r"((r)[8]),  "r"((r)[9]),  "r"((r)[10]), "r"((r)[11]), \
           "r"((r)[12]), "r"((r)[13]), "r"((r)[14]), "r"((r)[15]), \
           "r"((r)[16]), "r"((r)[17]), "r"((r)[18]), "r"((r)[19]), \
           "r"((r)[20]), "r"((r)[21]), "r"((r)[22]), "r"((r)[23]), \
           "r"((r)[24]), "r"((r)[25]), "r"((r)[26]), "r"((r)[27]), \
           "r"((r)[28]), "r"((r)[29]), "r"((r)[30]), "r"((r)[31]) \
        : "memory")

// SMEM descriptor: SW128, version=1 (Blackwell), LBO=1, SBO=64 (K-major)
__device__ __forceinline__ uint64_t make_desc(uint32_t addr) {
    const uint64_t base =
        (uint64_t(2)  << 61) | (uint64_t(1) << 46) |
        (uint64_t(64) << 32) | (uint64_t(1) << 16);
    return base | ((uint64_t)(addr >> 4) & 0x3FFF);
}

// SS form (A in SMEM)
__device__ __forceinline__ void tc_mma_tf32(uint32_t d_tmem, uint64_t a_desc,
                                            uint64_t b_desc, uint32_t idesc,
                                            uint32_t enable_d)
{
    asm volatile(
        "{\n\t"
        ".reg .pred p;\n\t"
        "setp.ne.u32 p, %5, 0;\n\t"
        "tcgen05.mma.cta_group::1.kind::tf32 [%0], %1, %2, %3, {%4, %4, %4, %4}, p;\n\t"
        "}"
        :: "r"(d_tmem), "l"(a_desc), "l"(b_desc), "r"(idesc), "r"(0u), "r"(enable_d)
        : "memory");
}

// TS form (A in TMEM)
__device__ __forceinline__ void tc_mma_tf32_ts(uint32_t d_tmem, uint32_t a_tmem,
                                               uint64_t b_desc, uint32_t idesc,
                                               uint32_t enable_d)
{
    asm volatile(
        "{\n\t"
        ".reg .pred p;\n\t"
        "setp.ne.u32 p, %5, 0;\n\t"
        "tcgen05.mma.cta_group::1.kind::tf32 [%0], [%1], %2, %3, {%4, %4, %4, %4}, p;\n\t"
        "}"
        :: "r"(d_tmem), "r"(a_tmem), "l"(b_desc), "r"(idesc), "r"(0u), "r"(enable_d)
        : "memory");
}

// idesc: dtype F32(1)<<4 | atype TF32(2)<<7 | btype TF32(2)<<10 | (N/8)<<17 | (M/16)<<24
#define TC_IDESC_G   ((1u << 4) | (2u << 7) | (2u << 10) | ((256u / 8u) << 17) | ((128u / 16u) << 24))
#define TC_IDESC_ATT ((1u << 4) | (2u << 7) | (2u << 10) | ((64u  / 8u) << 17) | ((128u / 16u) << 24))
#endif // HAS_TCGEN05

// ---------------------------------------------------------------------------
// Fused convert: fp32 -> tf32 bits, k-permuted, for x / w_attn / w_proj in
// ONE launch. (R15, measured)
// ---------------------------------------------------------------------------
#define NG_X  (MROWS * CDIM / 16)
#define NG_WA (3 * CDIM * CDIM / 16)
#define NG_WP (CDIM * CDIM / 16)
#define CVT_TPB 256
#define CVT_BLOCKS ((NG_X + NG_WA + NG_WP) / CVT_TPB)

__global__ void convert_all(const float* __restrict__ x,
                            const float* __restrict__ wa,
                            const float* __restrict__ wp,
                            unsigned* __restrict__ xt,
                            unsigned* __restrict__ wat,
                            unsigned* __restrict__ wpt)
{
    int gidx = blockIdx.x * CVT_TPB + threadIdx.x;
    const float* in;
    unsigned* out;
    if (gidx < NG_X) {
        in = x; out = xt;
    } else if (gidx < NG_X + NG_WA) {
        gidx -= NG_X; in = wa; out = wat;
    } else {
        gidx -= NG_X + NG_WA; in = wp; out = wpt;
    }
    const float4* ip = (const float4*)(in + (size_t)gidx * 16);
    float4 v0 = ip[0], v1 = ip[1], v2 = ip[2], v3 = ip[3];
    uint4 o0, o1, o2, o3;
    o0.x = f2tf32(v0.x); o0.y = f2tf32(v1.x); o0.z = f2tf32(v0.y); o0.w = f2tf32(v1.y);
    o1.x = f2tf32(v0.z); o1.y = f2tf32(v1.z); o1.z = f2tf32(v0.w); o1.w = f2tf32(v1.w);
    o2.x = f2tf32(v2.x); o2.y = f2tf32(v3.x); o2.z = f2tf32(v2.y); o2.w = f2tf32(v3.y);
    o3.x = f2tf32(v2.z); o3.y = f2tf32(v3.z); o3.z = f2tf32(v2.w); o3.w = f2tf32(v3.w);
    uint4* op = (uint4*)(out + (size_t)gidx * 16);
    op[0] = o0; op[1] = o1; op[2] = o2; op[3] = o3;
}

// ---------------------------------------------------------------------------
// GEMM (R10/R15 measured config — 2-buffer, 97KB smem, 2 CTAs/SM):
// C[M,N] = A[M,K] @ B[N,K]^T + bias[N], 128(M) x 256(N) tile.
// ---------------------------------------------------------------------------
#define TC_STAGE_BYTES 49152
#define HDR_BYTES      1024
#define GSMEM_TOTAL    (HDR_BYTES + 2 * TC_STAGE_BYTES)   // 99328
#define STAGE_WORDS    (384 * 16)

template<bool OUT_TF32>
__global__ __launch_bounds__(256, 1)
void gemm_tc(const unsigned* __restrict__ A, const unsigned* __restrict__ B,
             const float* __restrict__ bias, void* __restrict__ Cv,
             unsigned* __restrict__ vt,
             int M, int N, int K)
{
#if HAS_TCGEN05
    extern __shared__ unsigned smw[];
    const uint32_t sbase = (uint32_t)__cvta_generic_to_shared(smw);
    const uint32_t slot_tmem = sbase + 0;
    const uint32_t mbar      = sbase + 16;

    const int tid  = threadIdx.x;
    const int warp = tid >> 5;
    const int lane = tid & 31;

    const int m0 = blockIdx.y * 128;
    const int n0 = blockIdx.x * 256;

    if (warp == 0) {
        TC_ALLOC(slot_tmem, 256);
        TC_RELINQ();
    }
    if (tid == 0) MBAR_INIT(mbar, 1);
    __syncthreads();
    uint32_t tmem_base;
    asm volatile("ld.shared.b32 %0, [%1];" : "=r"(tmem_base) : "r"(slot_tmem));

    const int NC = K / 32;

    auto fill = [&](int c) {
        const uint32_t sb = sbase + HDR_BYTES + (uint32_t)(c & 1) * TC_STAGE_BYTES;
        const int k0 = c * 32;
#pragma unroll
        for (int i = 0; i < 12; i++) {
            const int o = tid + 256 * i;
            const int r = o >> 3;
            const int q = o & 7;
            if (r < 128) {
                const uint32_t sa = sb + (uint32_t)r * 128u + (uint32_t)((q ^ (r & 7)) << 4);
                cp_async16(sa, A + (size_t)(m0 + r) * K + k0 + q * 4);
            } else {
                const int rb = r - 128;
                const uint32_t sa = sb + 16384u + (uint32_t)rb * 128u + (uint32_t)((q ^ (rb & 7)) << 4);
                cp_async16(sa, B + (size_t)(n0 + rb) * K + k0 + q * 4);
            }
        }
    };

    fill(0);
    cp_commit();

    for (int c = 0; c < NC; c++) {
        if (c >= 1) MBAR_WAIT(mbar, (c - 1) & 1);
        if (c + 1 < NC) { fill(c + 1); cp_commit(); }
        if (c + 1 < NC) cp_wait<1>(); else cp_wait<0>();
        __syncthreads();

        if (warp == 0) {
            if (elect_one()) {
                FENCE_PROXY();
                const uint32_t sb = sbase + HDR_BYTES + (uint32_t)(c & 1) * TC_STAGE_BYTES;
                const uint64_t ad = make_desc(sb);
                const uint64_t bd = make_desc(sb + 16384u);
#pragma unroll
                for (int s = 0; s < 4; s++) {
                    tc_mma_tf32(tmem_base, ad + 2 * s, bd + 2 * s, TC_IDESC_G,
                                (c > 0 || s > 0) ? 1u : 0u);
                }
                TC_COMMIT(mbar);
            }
        }
        __syncthreads();
    }

    MBAR_WAIT(mbar, (NC - 1) & 1);
    TC_FENCE_AFTER();
    __syncthreads();

    unsigned* tr = smw + (HDR_BYTES / 4) + warp * (32 * 33);
    const int r0  = (warp & 3) * 32;
    const int ch0 = (warp >> 2) * 128;
    const bool is_v = OUT_TF32 && (n0 >= 2 * CDIM);
#pragma unroll
    for (int ch = 0; ch < 4; ch++) {
        const int cb = ch0 + ch * 32;
        uint32_t d[32];
        TC_LD_X32(d, tmem_base + cb);
        TC_WAIT_LD();
        if (is_v) {
            const int token = m0 + r0 + lane;
            unsigned* vb = vt + (size_t)(token >> 11) * 1024 * TSEQ + (token & 2047);
#pragma unroll
            for (int c = 0; c < 32; c++) {
                const int col = n0 + cb + c;
                vb[(size_t)(col - 2 * CDIM) * TSEQ] =
                    f2tf32(__uint_as_float(d[c]) + bias[col]);
            }
        } else {
#pragma unroll
            for (int j = 0; j < 32; j++) tr[lane * 33 + j] = d[j];
            __syncwarp();
            const int col = n0 + cb + lane;
            const float bv = bias[col];
            if (OUT_TF32) {
                unsigned* C = (unsigned*)Cv;
#pragma unroll 8
                for (int r = 0; r < 32; r++)
                    C[(size_t)(m0 + r0 + r) * N + col] = f2tf32(__uint_as_float(tr[r * 33 + lane]) + bv);
            } else {
                float* C = (float*)Cv;
#pragma unroll 8
                for (int r = 0; r < 32; r++)
                    C[(size_t)(m0 + r0 + r) * N + col] = __uint_as_float(tr[r * 33 + lane]) + bv;
            }
            __syncwarp();
        }
    }

    __syncthreads();
    if (warp == 0) {
        TC_DEALLOC(tmem_base, 256);
    }

#else
    // HMMA fallback (R4, measured; compile-only on this pass)
    (void)vt;
    extern __shared__ unsigned smg[];

    const int tid  = threadIdx.x;
    const int warp = tid >> 5;
    const int lane = tid & 31;
    const int g    = lane >> 2;
    const int t    = lane & 3;
    const int wm   = warp & 1;
    const int wn   = warp >> 1;

    const int m0 = blockIdx.y * 128;
    const int n0 = blockIdx.x * 256;

    const int lrow = tid >> 2;
    const int w4   = (tid & 3) * 4;

    const uint32_t sbase = (uint32_t)__cvta_generic_to_shared(smg);
    const int nk = K / 16;

    float acc[4][8][4];
#pragma unroll
    for (int i = 0; i < 4; i++)
#pragma unroll
        for (int j = 0; j < 8; j++)
#pragma unroll
            for (int c = 0; c < 4; c++) acc[i][j][c] = 0.0f;

    auto issue_stage = [&](int s) {
        const int sb   = (s & 3) * STAGE_WORDS;
        const int koff = s * 16;
#pragma unroll
        for (int c = 0; c < 2; c++) {
            const int r = lrow + 64 * c;
            const uint32_t sa = sbase + (uint32_t)(sb + r * 16 + (w4 ^ ((r & 3) << 2))) * 4u;
            cp_async16(sa, A + (size_t)(m0 + r) * K + koff + w4);
        }
#pragma unroll
        for (int c = 0; c < 4; c++) {
            const int r = lrow + 64 * c;
            const uint32_t sa = sbase + (uint32_t)(sb + 2048 + r * 16 + (w4 ^ ((r & 3) << 2))) * 4u;
            cp_async16(sa, B + (size_t)(n0 + r) * K + koff + w4);
        }
    };

    issue_stage(0); cp_commit();
    issue_stage(1); cp_commit();
    issue_stage(2); cp_commit();

    const int swz = (g & 3) << 2;

    for (int ks = 0; ks < nk; ks++) {
        cp_wait<2>();
        __syncthreads();
        if (ks + 3 < nk) issue_stage(ks + 3);
        cp_commit();

        const unsigned* as = smg + (ks & 3) * STAGE_WORDS;
        const unsigned* bs = as + 2048;

#pragma unroll
        for (int kk = 0; kk < 16; kk += 8) {
            const int off = (kk + 2 * t) ^ swz;
            uint2 a0[4], a1[4], bb[8];
#pragma unroll
            for (int im = 0; im < 4; im++) {
                const int rr0 = wm * 64 + im * 16 + g;
                a0[im] = *(const uint2*)(as + rr0 * 16 + off);
                a1[im] = *(const uint2*)(as + (rr0 + 8) * 16 + off);
            }
#pragma unroll
            for (int jn = 0; jn < 8; jn++) {
                const int rb = wn * 64 + jn * 8 + g;
                bb[jn] = *(const uint2*)(bs + rb * 16 + off);
            }
#pragma unroll
            for (int im = 0; im < 4; im++)
#pragma unroll
                for (int jn = 0; jn < 8; jn++)
                    mma_tf32(acc[im][jn],
                             a0[im].x, a1[im].x, a0[im].y, a1[im].y,
                             bb[jn].x, bb[jn].y);
        }
    }

#pragma unroll
    for (int jn = 0; jn < 8; jn++) {
        const int col = n0 + wn * 64 + jn * 8 + 2 * t;
        const float b0 = bias[col];
        const float b1 = bias[col + 1];
#pragma unroll
        for (int im = 0; im < 4; im++) {
            const int row = m0 + wm * 64 + im * 16 + g;
            if (OUT_TF32) {
                unsigned* C = (unsigned*)Cv;
                uint2 v0, v1;
                v0.x = f2tf32(acc[im][jn][0] + b0);
                v0.y = f2tf32(acc[im][jn][1] + b1);
                v1.x = f2tf32(acc[im][jn][2] + b0);
                v1.y = f2tf32(acc[im][jn][3] + b1);
                *(uint2*)(C + (size_t)row * N + col)       = v0;
                *(uint2*)(C + (size_t)(row + 8) * N + col) = v1;
            } else {
                float* C = (float*)Cv;
                float2 v0, v1;
                v0.x = acc[im][jn][0] + b0;
                v0.y = acc[im][jn][1] + b1;
                v1.x = acc[im][jn][2] + b0;
                v1.y = acc[im][jn][3] + b1;
                *(float2*)(C + (size_t)row * N + col)       = v0;
                *(float2*)(C + (size_t)(row + 8) * N + col) = v1;
            }
        }
    }
#endif
}

// ---------------------------------------------------------------------------
// Attention (causal), tcgen05 path — R16: deferred O accumulation.
// O(jt) is read at iteration jt+1 (after S(jt+1) wait), so the PV wait and
// LDTM O overlap with work instead of sitting on the tail of each iteration.
// Algebra: o += O(jt); o *= alpha(jt+1)  ==  (old) o *= alpha; ...; o += O.
// TMEM: S 0-63/64-127 (pipelined), O 128-191, P 192-255 (TS mma).
// ---------------------------------------------------------------------------
#define AQ_OFF 256
#define AK_OFF (AQ_OFF + 8192)
#define AV_OFF (AK_OFF + 8192)
#define ATTN_SMEM ((AV_OFF + 8192) * 4)   // 99328 B
#define QPAD 68
#define VPAD 72

__global__ __launch_bounds__(128, 2)
void attn_tc(const unsigned* __restrict__ qkv, const unsigned* __restrict__ vt,
             unsigned* __restrict__ y)
{
    extern __shared__ unsigned smu[];
    const int qtile = (int)gridDim.x - 1 - (int)blockIdx.x;   // heavy first
    const int bh    = blockIdx.y;
    const int b = bh >> 4;
    const int h = bh & 15;
    const int tid  = threadIdx.x;
    const int warp = tid >> 5;
    const int lane = tid & 31;
    const int q0   = qtile * 128;
    const int ntiles = 2 * qtile + 2;

    const unsigned* qbase = qkv + (size_t)b * TSEQ * 3 * CDIM + h * HD;
    const unsigned* kbase = qbase + CDIM;

#if HAS_TCGEN05
    const uint32_t sbase  = (uint32_t)__cvta_generic_to_shared(smu);
    const uint32_t slot   = sbase;
    const uint32_t mbar_s = sbase + 16;
    const uint32_t mbar_o = sbase + 32;
    const unsigned* vtb = vt + (size_t)bh * HD * TSEQ;

    if (warp == 0) { TC_ALLOC(slot, 256); TC_RELINQ(); }
    if (tid == 0)  { MBAR_INIT(mbar_s, 1); MBAR_INIT(mbar_o, 1); }
    __syncthreads();
    uint32_t tmem;
    asm volatile("ld.shared.b32 %0, [%1];" : "=r"(tmem) : "r"(slot));

    auto fillkv = [&](int jt) {
        const int buf = jt & 1;
        const int j0  = jt * 64;
#pragma unroll
        for (int i = 0; i < 8; i++) {
            const int gi = tid + 128 * i;
            const int c  = gi >> 9;
            const int r  = (gi >> 3) & 63;
            const int qg = gi & 7;
            const uint32_t sw = (uint32_t)((qg ^ (r & 7)) << 4);
            cp_async16(sbase + (uint32_t)(AK_OFF + buf * 4096 + c * 2048 + r * 32) * 4u + sw,
                       kbase + (size_t)(j0 + r) * (3 * CDIM) + c * 32 + qg * 4);
            cp_async16(sbase + (uint32_t)(AV_OFF + buf * 4096 + c * 2048 + r * 32) * 4u + sw,
                       vtb + (size_t)r * TSEQ + j0 + c * 32 + qg * 4);
        }
    };

    auto issueS = [&](int jt) {
        const uint32_t dst = tmem + 64u * (uint32_t)(jt & 1);
#pragma unroll
        for (int c = 0; c < 2; c++) {
            const uint64_t ad = make_desc(sbase + (uint32_t)(AQ_OFF + c * 4096) * 4u);
            const uint64_t bd = make_desc(sbase + (uint32_t)(AK_OFF + (jt & 1) * 4096 + c * 2048) * 4u);
#pragma unroll
            for (int s = 0; s < 4; s++)
                tc_mma_tf32(dst, ad + 2 * s, bd + 2 * s, TC_IDESC_ATT,
                            (c > 0 || s > 0) ? 1u : 0u);
        }
        TC_COMMIT(mbar_s);
    };

#pragma unroll
    for (int i = 0; i < 16; i++) {
        const int gi = tid + 128 * i;
        const int c  = gi >> 10;
        const int r  = (gi >> 3) & 127;
        const int qg = gi & 7;
        const uint32_t sw = (uint32_t)((qg ^ (r & 7)) << 4);
        cp_async16(sbase + (uint32_t)(AQ_OFF + c * 4096 + r * 32) * 4u + sw,
                   qbase + (size_t)(q0 + r) * (3 * CDIM) + c * 32 + qg * 4);
    }
    fillkv(0);
    cp_commit();
    cp_wait<0>();
    __syncthreads();

    if (warp == 0 && elect_one()) {
        FENCE_PROXY();
        issueS(0);
    }

    float o[64];
#pragma unroll
    for (int i = 0; i < 64; i++) o[i] = 0.0f;
    float m_ = -1e30f, l_ = 0.0f;
    const float cs = 0.125f * 1.4426950408889634f;   // scale * log2(e)
    const int myrow = q0 + warp * 32 + lane;
    const uint32_t pdst = tmem + 192u + ((uint32_t)warp << 21);

    for (int jt = 0; jt < ntiles; jt++) {
        MBAR_WAIT(mbar_s, jt & 1);
        TC_FENCE_AFTER();

        if (jt + 1 < ntiles) { fillkv(jt + 1); cp_commit(); }

        unsigned su[64];
        const uint32_t sb_t = tmem + 64u * (uint32_t)(jt & 1);
        TC_LD_X32(su, sb_t);
        TC_LD_X32(su + 32, sb_t + 32);
        TC_WAIT_LD();
        TC_FENCE_BEFORE();

        // ---- deferred O accumulation from previous tile ----
        // PV(jt-1) was issued a full tile ago; its wait is usually satisfied.
        if (jt > 0) {
            MBAR_WAIT(mbar_o, (jt - 1) & 1);
            TC_FENCE_AFTER();
            unsigned ou[64];
            TC_LD_X32(ou, tmem + 128);
            TC_LD_X32(ou + 32, tmem + 160);
            TC_WAIT_LD();
            TC_FENCE_BEFORE();
#pragma unroll
            for (int i = 0; i < 64; i++) o[i] += __uint_as_float(ou[i]);
        }

        // ---- per-thread softmax over full row (64 keys), in-place in su ----
        const int j0 = jt * 64;
        const bool masked = (jt >= 2 * qtile);
        float mx = -1e30f;
#pragma unroll
        for (int i = 0; i < 64; i++) {
            float x = __uint_as_float(su[i]) * cs;
            if (masked && (j0 + i > myrow)) x = -1e30f;
            su[i] = __float_as_uint(x);
            mx = fmaxf(mx, x);
        }
        const float mnew  = fmaxf(m_, mx);
        const float alpha = exp2f(m_ - mnew);
        m_ = mnew;
        float rs = 0.0f;
#pragma unroll
        for (int i = 0; i < 64; i++) {
            const float p = exp2f(__uint_as_float(su[i]) - mnew);
            rs += p;
            su[i] = f2tf32(p);
        }
        l_ = l_ * alpha + rs;
#pragma unroll
        for (int i = 0; i < 64; i++) o[i] *= alpha;

        TC_ST_X32(pdst, su);
        TC_ST_X32(pdst + 32, su + 32);
        TC_WAIT_ST();
        TC_FENCE_BEFORE();

        if (jt + 1 < ntiles) cp_wait<0>();
        __syncthreads();   // all warps: P in TMEM, prior O read, K/V(jt+1) in

        // ---- issue PV(jt) (overwrites O accumulator) and S(jt+1) ----
        if (warp == 0 && elect_one()) {
            TC_FENCE_AFTER();
#pragma unroll
            for (int c = 0; c < 2; c++) {
                const uint64_t bd = make_desc(sbase + (uint32_t)(AV_OFF + (jt & 1) * 4096 + c * 2048) * 4u);
#pragma unroll
                for (int s = 0; s < 4; s++) {
                    const uint32_t a_t = tmem + 192u + (uint32_t)((c * 4 + s) * 8);
                    tc_mma_tf32_ts(tmem + 128, a_t, bd + 2 * s, TC_IDESC_ATT,
                                   (c > 0 || s > 0) ? 1u : 0u);
                }
            }
            TC_COMMIT(mbar_o);
            if (jt + 1 < ntiles) issueS(jt + 1);
        }
    }

    // final deferred O accumulate
    {
        MBAR_WAIT(mbar_o, (ntiles - 1) & 1);
        TC_FENCE_AFTER();
        unsigned ou[64];
        TC_LD_X32(ou, tmem + 128);
        TC_LD_X32(ou + 32, tmem + 160);
        TC_WAIT_LD();
        TC_FENCE_BEFORE();
#pragma unroll
        for (int i = 0; i < 64; i++) o[i] += __uint_as_float(ou[i]);
    }

    const float inv = 1.0f / l_;
    unsigned* yrow = y + (size_t)(b * TSEQ + q0 + warp * 32 + lane) * CDIM + h * HD;
#pragma unroll
    for (int g16 = 0; g16 < 4; g16++) {
        const float* ob = o + g16 * 16;
        uint4 w0, w1, w2, w3;
        w0.x = f2tf32(ob[0]  * inv); w0.y = f2tf32(ob[4]  * inv);
        w0.z = f2tf32(ob[1]  * inv); w0.w = f2tf32(ob[5]  * inv);
        w1.x = f2tf32(ob[2]  * inv); w1.y = f2tf32(ob[6]  * inv);
        w1.z = f2tf32(ob[3]  * inv); w1.w = f2tf32(ob[7]  * inv);
        w2.x = f2tf32(ob[8]  * inv); w2.y = f2tf32(ob[12] * inv);
        w2.z = f2tf32(ob[9]  * inv); w2.w = f2tf32(ob[13] * inv);
        w3.x = f2tf32(ob[10] * inv); w3.y = f2tf32(ob[14] * inv);
        w3.z = f2tf32(ob[11] * inv); w3.w = f2tf32(ob[15] * inv);
        *(uint4*)(yrow + g16 * 16 + 0)  = w0;
        *(uint4*)(yrow + g16 * 16 + 4)  = w1;
        *(uint4*)(yrow + g16 * 16 + 8)  = w2;
        *(uint4*)(yrow + g16 * 16 + 12) = w3;
    }

    __syncthreads();
    if (warp == 0) TC_DEALLOC(tmem, 256);

#else
    // =============== HMMA fallback (compile-only on compute_103 pass) =======
    (void)vt;
    unsigned* Qs = smu;
    unsigned* Ps = Qs + 64 * QPAD;
    unsigned* Ks = Ps + 64 * QPAD;
    unsigned* Vs = Ks + 64 * QPAD;
    const unsigned* vbase = qbase + 2 * CDIM;

    const int g = lane >> 2;
    const int t = lane & 3;
    const int w16 = warp * 16;
    const int qq0 = qtile * 128;

    for (int idx = tid; idx < 64 * 16; idx += 128) {
        const int r  = idx >> 4;
        const int c4 = (idx & 15) * 4;
        *(uint4*)(Qs + r * QPAD + c4) =
            *(const uint4*)(qbase + (size_t)(qq0 + r) * (3 * CDIM) + c4);
    }

    float m_i[2], l_i[2], o[8][4];
#pragma unroll
    for (int rr = 0; rr < 2; rr++) { m_i[rr] = -1e30f; l_i[rr] = 0.0f; }
#pragma unroll
    for (int jn = 0; jn < 8; jn++)
#pragma unroll
        for (int c = 0; c < 4; c++) o[jn][c] = 0.0f;

    const float scale = 0.125f;

    for (int jt = 0; jt < ntiles; jt++) {
        const int j0 = jt * 64;
        __syncthreads();
        for (int idx = tid; idx < 64 * 16; idx += 128) {
            const int r  = idx >> 4;
            const int c4 = (idx & 15) * 4;
            *(uint4*)(Ks + r * QPAD + c4) =
                *(const uint4*)(kbase + (size_t)(j0 + r) * (3 * CDIM) + c4);
            *(uint4*)(Vs + r * QPAD + c4) =
                *(const uint4*)(vbase + (size_t)(j0 + r) * (3 * CDIM) + c4);
        }
        __syncthreads();

        float s[8][4];
#pragma unroll
        for (int jn = 0; jn < 8; jn++)
#pragma unroll
            for (int c = 0; c < 4; c++) s[jn][c] = 0.0f;

#pragma unroll
        for (int kc = 0; kc < 64; kc += 8) {
            unsigned a0 = Qs[(w16 + g    ) * QPAD + kc + t];
            unsigned a1 = Qs[(w16 + g + 8) * QPAD + kc + t];
            unsigned a2 = Qs[(w16 + g    ) * QPAD + kc + t + 4];
            unsigned a3 = Qs[(w16 + g + 8) * QPAD + kc + t + 4];
#pragma unroll
            for (int jn = 0; jn < 8; jn++) {
                unsigned b0 = Ks[(jn * 8 + g) * QPAD + kc + t];
                unsigned b1 = Ks[(jn * 8 + g) * QPAD + kc + t + 4];
                mma_tf32(s[jn], a0, a1, a2, a3, b0, b1);
            }
        }

#pragma unroll
        for (int rr = 0; rr < 2; rr++) {
            const int qrow = qq0 + w16 + g + 8 * rr;
            float mx = -1e30f;
#pragma unroll
            for (int jn = 0; jn < 8; jn++) {
                const int col = j0 + jn * 8 + 2 * t;
                float v0 = s[jn][2 * rr + 0] * scale;
                float v1 = s[jn][2 * rr + 1] * scale;
                v0 = (col     <= qrow) ? v0 : -1e30f;
                v1 = (col + 1 <= qrow) ? v1 : -1e30f;
                s[jn][2 * rr + 0] = v0;
                s[jn][2 * rr + 1] = v1;
                mx = fmaxf(mx, fmaxf(v0, v1));
            }
            mx = fmaxf(mx, __shfl_xor_sync(0xffffffffu, mx, 1));
            mx = fmaxf(mx, __shfl_xor_sync(0xffffffffu, mx, 2));
            const float mnew  = fmaxf(m_i[rr], mx);
            const float alpha = __expf(m_i[rr] - mnew);
            float rs = 0.0f;
            unsigned* prow = Ps + (w16 + g + 8 * rr) * QPAD;
#pragma unroll
            for (int jn = 0; jn < 8; jn++) {
                const float p0 = __expf(s[jn][2 * rr + 0] - mnew);
                const float p1 = __expf(s[jn][2 * rr + 1] - mnew);
                rs += p0 + p1;
                prow[jn * 8 + 2 * t    ] = f2tf32(p0);
                prow[jn * 8 + 2 * t + 1] = f2tf32(p1);
            }
            rs += __shfl_xor_sync(0xffffffffu, rs, 1);
            rs += __shfl_xor_sync(0xffffffffu, rs, 2);
            l_i[rr] = l_i[rr] * alpha + rs;
            m_i[rr] = mnew;
#pragma unroll
            for (int jn = 0; jn < 8; jn++) {
                o[jn][2 * rr + 0] *= alpha;
                o[jn][2 * rr + 1] *= alpha;
            }
        }
        __syncwarp();

#pragma unroll
        for (int kc = 0; kc < 64; kc += 8) {
            unsigned a0 = Ps[(w16 + g    ) * QPAD + kc + t];
            unsigned a1 = Ps[(w16 + g + 8) * QPAD + kc + t];
            unsigned a2 = Ps[(w16 + g    ) * QPAD + kc + t + 4];
            unsigned a3 = Ps[(w16 + g + 8) * QPAD + kc + t + 4];
#pragma unroll
            for (int jn = 0; jn < 8; jn++) {
                unsigned b0 = Vs[(kc + t    ) * QPAD + jn * 8 + g];
                unsigned b1 = Vs[(kc + t + 4) * QPAD + jn * 8 + g];
                mma_tf32(o[jn], a0, a1, a2, a3, b0, b1);
            }
        }
    }

    const float inv0 = 1.0f / l_i[0];
    const float inv1 = 1.0f / l_i[1];
    const int row0 = qq0 + w16 + g;
    unsigned* y0 = y + (size_t)b * TSEQ * CDIM + (size_t)row0 * CDIM;
    unsigned* y1 = y0 + 8 * CDIM;
#pragma unroll
    for (int jn = 0; jn < 8; jn++) {
        const int d  = h * HD + jn * 8 + 2 * t;
        const int p0 = (d & ~15) | perm16((d    ) & 15);
        const int p1 = (d & ~15) | perm16((d + 1) & 15);
        y0[p0] = f2tf32(o[jn][0] * inv0);
        y0[p1] = f2tf32(o[jn][1] * inv0);
        y1[p0] = f2tf32(o[jn][2] * inv1);
        y1[p1] = f2tf32(o[jn][3] * inv1);
    }
#endif
}

// ---------------------------------------------------------------------------
extern "C" void kernel_launch(void* const* d_in, const int* in_sizes, int n_in,
                              void* d_out, int out_size)
{
    (void)in_sizes; (void)n_in; (void)out_size;
    const float* x      = (const float*)d_in[0];
    const float* w_attn = (const float*)d_in[1];
    const float* b_attn = (const float*)d_in[2];
    const float* w_proj = (const float*)d_in[3];
    const float* b_proj = (const float*)d_in[4];
    float* out = (float*)d_out;

    unsigned *xt, *wat, *wpt, *qkv, *vtg, *yt;
    cudaGetSymbolAddress((void**)&xt,  g_xt);
    cudaGetSymbolAddress((void**)&wat, g_wat);
    cudaGetSymbolAddress((void**)&wpt, g_wpt);
    cudaGetSymbolAddress((void**)&qkv, g_qkv);
    cudaGetSymbolAddress((void**)&vtg, g_vt);
    cudaGetSymbolAddress((void**)&yt,  g_yt);

    cudaFuncSetAttribute(gemm_tc<true>,  cudaFuncAttributeMaxDynamicSharedMemorySize, GSMEM_TOTAL);
    cudaFuncSetAttribute(gemm_tc<false>, cudaFuncAttributeMaxDynamicSharedMemorySize, GSMEM_TOTAL);
    cudaFuncSetAttribute(attn_tc,        cudaFuncAttributeMaxDynamicSharedMemorySize, ATTN_SMEM);

    // 0) convert + permute all inputs to tf32 in ONE launch
    convert_all<<<CVT_BLOCKS, CVT_TPB>>>(x, w_attn, w_proj, xt, wat, wpt);

    // 1) QKV projection (128x256 tiles, R10 config) -> q,k + V^T
    gemm_tc<true><<<dim3(3 * CDIM / 256, MROWS / 128), 256, GSMEM_TOTAL>>>(
        xt, wat, b_attn, qkv, vtg, MROWS, 3 * CDIM, CDIM);

    // 2) causal flash attention (tcgen05, deferred O accumulation) -> y
    attn_tc<<<dim3(TSEQ / 128, BATCH * NHEAD), 128, ATTN_SMEM>>>(qkv, vtg, yt);

    // 3) output projection (128x256 tiles, R10 config) -> fp32
    gemm_tc<false><<<dim3(CDIM / 256, MROWS / 128), 256, GSMEM_TOTAL>>>(
        yt, wpt, b_proj, out, nullptr, MROWS, CDIM, CDIM);
}

// round 17
// speedup vs baseline: 1.0330x; 1.0330x over previous
#include <cuda_runtime.h>
#include <cuda_bf16.h>
#include <cstdint>

// Problem constants
#define BATCH 4
#define TSEQ  2048
#define CDIM  1024
#define NHEAD 16
#define HD    64
#define MROWS (BATCH * TSEQ)   // 8192

// Arch feature gate: tcgen05 only exists on the 'a' targets.
#if defined(__CUDA_ARCH_FEAT_SM103_ALL) || defined(__CUDA_ARCH_FEAT_SM100_ALL) || defined(__CUDA_ARCH_FEAT_SM101_ALL)
#define HAS_TCGEN05 1
#else
#define HAS_TCGEN05 0
#endif

// Scratch (device globals; no allocations allowed)
__device__ unsigned g_xt [(size_t)MROWS * CDIM];        // x, tf32, k-permuted
__device__ unsigned g_wat[(size_t)3 * CDIM * CDIM];     // w_attn, tf32, k-permuted
__device__ unsigned g_wpt[(size_t)CDIM * CDIM];         // w_proj, tf32, k-permuted
__device__ unsigned g_qkv[(size_t)MROWS * 3 * CDIM];    // q,k tf32 bits natural
__device__ unsigned g_vt [(size_t)BATCH * NHEAD * HD * TSEQ]; // V^T tf32 bits [b,h,d,t]
__device__ unsigned g_yt [(size_t)MROWS * CDIM];        // y, tf32 bits, k-permuted

// ---------------------------------------------------------------------------
// generic helpers
// ---------------------------------------------------------------------------
__device__ __forceinline__ unsigned f2tf32(float f) {
    unsigned u;
    asm("cvt.rna.tf32.f32 %0, %1;" : "=r"(u) : "f"(f));
    return u;
}

__device__ __forceinline__ void mma_tf32(float c[4],
                                         unsigned a0, unsigned a1, unsigned a2, unsigned a3,
                                         unsigned b0, unsigned b1)
{
    asm volatile(
        "mma.sync.aligned.m16n8k8.row.col.f32.tf32.tf32.f32 "
        "{%0,%1,%2,%3}, {%4,%5,%6,%7}, {%8,%9}, {%0,%1,%2,%3};"
        : "+f"(c[0]), "+f"(c[1]), "+f"(c[2]), "+f"(c[3])
        : "r"(a0), "r"(a1), "r"(a2), "r"(a3), "r"(b0), "r"(b1));
}

__device__ __forceinline__ void cp_async16(uint32_t saddr, const void* gptr) {
    asm volatile("cp.async.cg.shared.global [%0], [%1], 16;" :: "r"(saddr), "l"(gptr));
}
__device__ __forceinline__ void cp_commit() {
    asm volatile("cp.async.commit_group;");
}
template<int N_>
__device__ __forceinline__ void cp_wait() {
    asm volatile("cp.async.wait_group %0;" :: "n"(N_));
}

__device__ __forceinline__ uint32_t elect_one() {
    uint32_t pred;
    asm volatile("{\n\t.reg .pred p;\n\telect.sync _|p, 0xFFFFFFFF;\n\t"
                 "selp.b32 %0, 1, 0, p;\n\t}" : "=r"(pred));
    return pred;
}

// k-permutation within 16-word groups (HMMA fragment pairing; dot-product invariant)
__device__ __host__ __forceinline__ int perm16(int i) {
    int lo = i & 7;
    return ((i >> 3) << 3) | ((lo & 3) << 1) | (lo >> 2);
}

// ---------------------------------------------------------------------------
// mbarrier helpers (valid on all targets)
// ---------------------------------------------------------------------------
#define MBAR_INIT(addr, cnt) \
    asm volatile("mbarrier.init.shared.b64 [%0], %1;" :: "r"(addr), "r"(cnt) : "memory")

#define MBAR_WAIT(addr, phase) do {                                             \
    asm volatile(                                                               \
        "{\n\t.reg .pred P1;\n\t"                                               \
        "WAIT_%=:\n\t"                                                          \
        "mbarrier.try_wait.parity.acquire.cta.shared::cta.b64 P1, [%0], %1, 0x989680;\n\t" \
        "@P1 bra.uni DONE_%=;\n\t"                                              \
        "bra.uni WAIT_%=;\n\t"                                                  \
        "DONE_%=:\n\t}"                                                         \
        :: "r"(addr), "r"(phase) : "memory");                                   \
} while (0)

// ---------------------------------------------------------------------------
// tcgen05 helpers — only instantiated under HAS_TCGEN05
// ---------------------------------------------------------------------------
#if HAS_TCGEN05
#define TC_ALLOC(slot, n) \
    asm volatile("tcgen05.alloc.cta_group::1.sync.aligned.shared::cta.b32 [%0], %1;" \
                 :: "r"(slot), "r"(n) : "memory")
#define TC_RELINQ() \
    asm volatile("tcgen05.relinquish_alloc_permit.cta_group::1.sync.aligned;")
#define TC_DEALLOC(base, n) \
    asm volatile("tcgen05.dealloc.cta_group::1.sync.aligned.b32 %0, %1;" :: "r"(base), "r"(n))
#define TC_COMMIT(mbar) \
    asm volatile("tcgen05.commit.cta_group::1.mbarrier::arrive::one.shared::cluster.b64 [%0];" \
                 :: "r"(mbar) : "memory")
#define TC_FENCE_AFTER()   asm volatile("tcgen05.fence::after_thread_sync;" ::: "memory")
#define TC_FENCE_BEFORE()  asm volatile("tcgen05.fence::before_thread_sync;" ::: "memory")
#define TC_WAIT_LD()       asm volatile("tcgen05.wait::ld.sync.aligned;" ::: "memory")
#define TC_WAIT_ST()       asm volatile("tcgen05.wait::st.sync.aligned;" ::: "memory")
#define FENCE_PROXY()      asm volatile("fence.proxy.async.shared::cta;" ::: "memory")

#define TC_LD_X32(r, addr) \
    asm volatile( \
        "tcgen05.ld.sync.aligned.32x32b.x32.b32 " \
        "{%0, %1, %2, %3, %4, %5, %6, %7, " \
        " %8, %9, %10, %11, %12, %13, %14, %15, " \
        " %16, %17, %18, %19, %20, %21, %22, %23, " \
        " %24, %25, %26, %27, %28, %29, %30, %31}, [%32];" \
        : "=r"((r)[0]),  "=r"((r)[1]),  "=r"((r)[2]),  "=r"((r)[3]), \
          "=r"((r)[4]),  "=r"((r)[5]),  "=r"((r)[6]),  "=r"((r)[7]), \
          "=r"((r)[8]),  "=r"((r)[9]),  "=r"((r)[10]), "=r"((r)[11]), \
          "=r"((r)[12]), "=r"((r)[13]), "=r"((r)[14]), "=r"((r)[15]), \
          "=r"((r)[16]), "=r"((r)[17]), "=r"((r)[18]), "=r"((r)[19]), \
          "=r"((r)[20]), "=r"((r)[21]), "=r"((r)[22]), "=r"((r)[23]), \
          "=r"((r)[24]), "=r"((r)[25]), "=r"((r)[26]), "=r"((r)[27]), \
          "=r"((r)[28]), "=r"((r)[29]), "=r"((r)[30]), "=r"((r)[31]) \
        : "r"(addr))

#define TC_ST_X32(addr, r) \
    asm volatile( \
        "tcgen05.st.sync.aligned.32x32b.x32.b32 [%0], " \
        "{%1, %2, %3, %4, %5, %6, %7, %8, " \
        " %9, %10, %11, %12, %13, %14, %15, %16, " \
        " %17, %18, %19, %20, %21, %22, %23, %24, " \
        " %25, %26, %27, %28, %29, %30, %31, %32};" \
        :: "r"(addr), \
           "r"((r)[0]),  "r"((r)[1]),  "r"((r)[2]),  "r"((r)[3]), \
           "r"((r)[4]),  "r"((r)[5]),  "r"((r)[6]),  "r"((r)[7]), \
           "r"((r)[8]),  "r"((r)[9]),  "r"((r)[10]), "r"((r)[11]), \
           "r"((r)[12]), "r"((r)[13]), "r"((r)[14]), "r"((r)[15]), \
           "r"((r)[16]), "r"((r)[17]), "r"((r)[18]), "r"((r)[19]), \
           "r"((r)[20]), "r"((r)[21]), "r"((r)[22]), "r"((r)[23]), \
           "r"((r)[24]), "r"((r)[25]), "r"((r)[26]), "r"((r)[27]), \
           "r"((r)[28]), "r"((r)[29]), "r"((r)[30]), "r"((r)[31]) \
        : "memory")

// SMEM descriptor: SW128, version=1 (Blackwell), LBO=1, SBO=64 (K-major)
__device__ __forceinline__ uint64_t make_desc(uint32_t addr) {
    const uint64_t base =
        (uint64_t(2)  << 61) | (uint64_t(1) << 46) |
        (uint64_t(64) << 32) | (uint64_t(1) << 16);
    return base | ((uint64_t)(addr >> 4) & 0x3FFF);
}

// SS form (A in SMEM)
__device__ __forceinline__ void tc_mma_tf32(uint32_t d_tmem, uint64_t a_desc,
                                            uint64_t b_desc, uint32_t idesc,
                                            uint32_t enable_d)
{
    asm volatile(
        "{\n\t"
        ".reg .pred p;\n\t"
        "setp.ne.u32 p, %5, 0;\n\t"
        "tcgen05.mma.cta_group::1.kind::tf32 [%0], %1, %2, %3, {%4, %4, %4, %4}, p;\n\t"
        "}"
        :: "r"(d_tmem), "l"(a_desc), "l"(b_desc), "r"(idesc), "r"(0u), "r"(enable_d)
        : "memory");
}

// TS form (A in TMEM)
__device__ __forceinline__ void tc_mma_tf32_ts(uint32_t d_tmem, uint32_t a_tmem,
                                               uint64_t b_desc, uint32_t idesc,
                                               uint32_t enable_d)
{
    asm volatile(
        "{\n\t"
        ".reg .pred p;\n\t"
        "setp.ne.u32 p, %5, 0;\n\t"
        "tcgen05.mma.cta_group::1.kind::tf32 [%0], [%1], %2, %3, {%4, %4, %4, %4}, p;\n\t"
        "}"
        :: "r"(d_tmem), "r"(a_tmem), "l"(b_desc), "r"(idesc), "r"(0u), "r"(enable_d)
        : "memory");
}

// idesc: dtype F32(1)<<4 | atype TF32(2)<<7 | btype TF32(2)<<10 | (N/8)<<17 | (M/16)<<24
#define TC_IDESC_G   ((1u << 4) | (2u << 7) | (2u << 10) | ((256u / 8u) << 17) | ((128u / 16u) << 24))
#define TC_IDESC_ATT ((1u << 4) | (2u << 7) | (2u << 10) | ((64u  / 8u) << 17) | ((128u / 16u) << 24))
#endif // HAS_TCGEN05

// ---------------------------------------------------------------------------
// Fused convert: fp32 -> tf32 bits, k-permuted, for x / w_attn / w_proj in
// ONE launch. (R15, measured)
// ---------------------------------------------------------------------------
#define NG_X  (MROWS * CDIM / 16)
#define NG_WA (3 * CDIM * CDIM / 16)
#define NG_WP (CDIM * CDIM / 16)
#define CVT_TPB 256
#define CVT_BLOCKS ((NG_X + NG_WA + NG_WP) / CVT_TPB)

__global__ void convert_all(const float* __restrict__ x,
                            const float* __restrict__ wa,
                            const float* __restrict__ wp,
                            unsigned* __restrict__ xt,
                            unsigned* __restrict__ wat,
                            unsigned* __restrict__ wpt)
{
    int gidx = blockIdx.x * CVT_TPB + threadIdx.x;
    const float* in;
    unsigned* out;
    if (gidx < NG_X) {
        in = x; out = xt;
    } else if (gidx < NG_X + NG_WA) {
        gidx -= NG_X; in = wa; out = wat;
    } else {
        gidx -= NG_X + NG_WA; in = wp; out = wpt;
    }
    const float4* ip = (const float4*)(in + (size_t)gidx * 16);
    float4 v0 = ip[0], v1 = ip[1], v2 = ip[2], v3 = ip[3];
    uint4 o0, o1, o2, o3;
    o0.x = f2tf32(v0.x); o0.y = f2tf32(v1.x); o0.z = f2tf32(v0.y); o0.w = f2tf32(v1.y);
    o1.x = f2tf32(v0.z); o1.y = f2tf32(v1.z); o1.z = f2tf32(v0.w); o1.w = f2tf32(v1.w);
    o2.x = f2tf32(v2.x); o2.y = f2tf32(v3.x); o2.z = f2tf32(v2.y); o2.w = f2tf32(v3.y);
    o3.x = f2tf32(v2.z); o3.y = f2tf32(v3.z); o3.z = f2tf32(v2.w); o3.w = f2tf32(v3.w);
    uint4* op = (uint4*)(out + (size_t)gidx * 16);
    op[0] = o0; op[1] = o1; op[2] = o2; op[3] = o3;
}

// ---------------------------------------------------------------------------
// GEMM (R10/R15 measured config — 2-buffer, 97KB smem, 2 CTAs/SM):
// C[M,N] = A[M,K] @ B[N,K]^T + bias[N], 128(M) x 256(N) tile.
// ---------------------------------------------------------------------------
#define TC_STAGE_BYTES 49152
#define HDR_BYTES      1024
#define GSMEM_TOTAL    (HDR_BYTES + 2 * TC_STAGE_BYTES)   // 99328
#define STAGE_WORDS    (384 * 16)

template<bool OUT_TF32>
__global__ __launch_bounds__(256, 1)
void gemm_tc(const unsigned* __restrict__ A, const unsigned* __restrict__ B,
             const float* __restrict__ bias, void* __restrict__ Cv,
             unsigned* __restrict__ vt,
             int M, int N, int K)
{
#if HAS_TCGEN05
    extern __shared__ unsigned smw[];
    const uint32_t sbase = (uint32_t)__cvta_generic_to_shared(smw);
    const uint32_t slot_tmem = sbase + 0;
    const uint32_t mbar      = sbase + 16;

    const int tid  = threadIdx.x;
    const int warp = tid >> 5;
    const int lane = tid & 31;

    const int m0 = blockIdx.y * 128;
    const int n0 = blockIdx.x * 256;

    if (warp == 0) {
        TC_ALLOC(slot_tmem, 256);
        TC_RELINQ();
    }
    if (tid == 0) MBAR_INIT(mbar, 1);
    __syncthreads();
    uint32_t tmem_base;
    asm volatile("ld.shared.b32 %0, [%1];" : "=r"(tmem_base) : "r"(slot_tmem));

    const int NC = K / 32;

    auto fill = [&](int c) {
        const uint32_t sb = sbase + HDR_BYTES + (uint32_t)(c & 1) * TC_STAGE_BYTES;
        const int k0 = c * 32;
#pragma unroll
        for (int i = 0; i < 12; i++) {
            const int o = tid + 256 * i;
            const int r = o >> 3;
            const int q = o & 7;
            if (r < 128) {
                const uint32_t sa = sb + (uint32_t)r * 128u + (uint32_t)((q ^ (r & 7)) << 4);
                cp_async16(sa, A + (size_t)(m0 + r) * K + k0 + q * 4);
            } else {
                const int rb = r - 128;
                const uint32_t sa = sb + 16384u + (uint32_t)rb * 128u + (uint32_t)((q ^ (rb & 7)) << 4);
                cp_async16(sa, B + (size_t)(n0 + rb) * K + k0 + q * 4);
            }
        }
    };

    fill(0);
    cp_commit();

    for (int c = 0; c < NC; c++) {
        if (c >= 1) MBAR_WAIT(mbar, (c - 1) & 1);
        if (c + 1 < NC) { fill(c + 1); cp_commit(); }
        if (c + 1 < NC) cp_wait<1>(); else cp_wait<0>();
        __syncthreads();

        if (warp == 0) {
            if (elect_one()) {
                FENCE_PROXY();
                const uint32_t sb = sbase + HDR_BYTES + (uint32_t)(c & 1) * TC_STAGE_BYTES;
                const uint64_t ad = make_desc(sb);
                const uint64_t bd = make_desc(sb + 16384u);
#pragma unroll
                for (int s = 0; s < 4; s++) {
                    tc_mma_tf32(tmem_base, ad + 2 * s, bd + 2 * s, TC_IDESC_G,
                                (c > 0 || s > 0) ? 1u : 0u);
                }
                TC_COMMIT(mbar);
            }
        }
        __syncthreads();
    }

    MBAR_WAIT(mbar, (NC - 1) & 1);
    TC_FENCE_AFTER();
    __syncthreads();

    unsigned* tr = smw + (HDR_BYTES / 4) + warp * (32 * 33);
    const int r0  = (warp & 3) * 32;
    const int ch0 = (warp >> 2) * 128;
    const bool is_v = OUT_TF32 && (n0 >= 2 * CDIM);
#pragma unroll
    for (int ch = 0; ch < 4; ch++) {
        const int cb = ch0 + ch * 32;
        uint32_t d[32];
        TC_LD_X32(d, tmem_base + cb);
        TC_WAIT_LD();
        if (is_v) {
            const int token = m0 + r0 + lane;
            unsigned* vb = vt + (size_t)(token >> 11) * 1024 * TSEQ + (token & 2047);
#pragma unroll
            for (int c = 0; c < 32; c++) {
                const int col = n0 + cb + c;
                vb[(size_t)(col - 2 * CDIM) * TSEQ] =
                    f2tf32(__uint_as_float(d[c]) + bias[col]);
            }
        } else {
#pragma unroll
            for (int j = 0; j < 32; j++) tr[lane * 33 + j] = d[j];
            __syncwarp();
            const int col = n0 + cb + lane;
            const float bv = bias[col];
            if (OUT_TF32) {
                unsigned* C = (unsigned*)Cv;
#pragma unroll 8
                for (int r = 0; r < 32; r++)
                    C[(size_t)(m0 + r0 + r) * N + col] = f2tf32(__uint_as_float(tr[r * 33 + lane]) + bv);
            } else {
                float* C = (float*)Cv;
#pragma unroll 8
                for (int r = 0; r < 32; r++)
                    C[(size_t)(m0 + r0 + r) * N + col] = __uint_as_float(tr[r * 33 + lane]) + bv;
            }
            __syncwarp();
        }
    }

    __syncthreads();
    if (warp == 0) {
        TC_DEALLOC(tmem_base, 256);
    }

#else
    // HMMA fallback (R4, measured; compile-only on this pass)
    (void)vt;
    extern __shared__ unsigned smg[];

    const int tid  = threadIdx.x;
    const int warp = tid >> 5;
    const int lane = tid & 31;
    const int g    = lane >> 2;
    const int t    = lane & 3;
    const int wm   = warp & 1;
    const int wn   = warp >> 1;

    const int m0 = blockIdx.y * 128;
    const int n0 = blockIdx.x * 256;

    const int lrow = tid >> 2;
    const int w4   = (tid & 3) * 4;

    const uint32_t sbase = (uint32_t)__cvta_generic_to_shared(smg);
    const int nk = K / 16;

    float acc[4][8][4];
#pragma unroll
    for (int i = 0; i < 4; i++)
#pragma unroll
        for (int j = 0; j < 8; j++)
#pragma unroll
            for (int c = 0; c < 4; c++) acc[i][j][c] = 0.0f;

    auto issue_stage = [&](int s) {
        const int sb   = (s & 3) * STAGE_WORDS;
        const int koff = s * 16;
#pragma unroll
        for (int c = 0; c < 2; c++) {
            const int r = lrow + 64 * c;
            const uint32_t sa = sbase + (uint32_t)(sb + r * 16 + (w4 ^ ((r & 3) << 2))) * 4u;
            cp_async16(sa, A + (size_t)(m0 + r) * K + koff + w4);
        }
#pragma unroll
        for (int c = 0; c < 4; c++) {
            const int r = lrow + 64 * c;
            const uint32_t sa = sbase + (uint32_t)(sb + 2048 + r * 16 + (w4 ^ ((r & 3) << 2))) * 4u;
            cp_async16(sa, B + (size_t)(n0 + r) * K + koff + w4);
        }
    };

    issue_stage(0); cp_commit();
    issue_stage(1); cp_commit();
    issue_stage(2); cp_commit();

    const int swz = (g & 3) << 2;

    for (int ks = 0; ks < nk; ks++) {
        cp_wait<2>();
        __syncthreads();
        if (ks + 3 < nk) issue_stage(ks + 3);
        cp_commit();

        const unsigned* as = smg + (ks & 3) * STAGE_WORDS;
        const unsigned* bs = as + 2048;

#pragma unroll
        for (int kk = 0; kk < 16; kk += 8) {
            const int off = (kk + 2 * t) ^ swz;
            uint2 a0[4], a1[4], bb[8];
#pragma unroll
            for (int im = 0; im < 4; im++) {
                const int rr0 = wm * 64 + im * 16 + g;
                a0[im] = *(const uint2*)(as + rr0 * 16 + off);
                a1[im] = *(const uint2*)(as + (rr0 + 8) * 16 + off);
            }
#pragma unroll
            for (int jn = 0; jn < 8; jn++) {
                const int rb = wn * 64 + jn * 8 + g;
                bb[jn] = *(const uint2*)(bs + rb * 16 + off);
            }
#pragma unroll
            for (int im = 0; im < 4; im++)
#pragma unroll
                for (int jn = 0; jn < 8; jn++)
                    mma_tf32(acc[im][jn],
                             a0[im].x, a1[im].x, a0[im].y, a1[im].y,
                             bb[jn].x, bb[jn].y);
        }
    }

#pragma unroll
    for (int jn = 0; jn < 8; jn++) {
        const int col = n0 + wn * 64 + jn * 8 + 2 * t;
        const float b0 = bias[col];
        const float b1 = bias[col + 1];
#pragma unroll
        for (int im = 0; im < 4; im++) {
            const int row = m0 + wm * 64 + im * 16 + g;
            if (OUT_TF32) {
                unsigned* C = (unsigned*)Cv;
                uint2 v0, v1;
                v0.x = f2tf32(acc[im][jn][0] + b0);
                v0.y = f2tf32(acc[im][jn][1] + b1);
                v1.x = f2tf32(acc[im][jn][2] + b0);
                v1.y = f2tf32(acc[im][jn][3] + b1);
                *(uint2*)(C + (size_t)row * N + col)       = v0;
                *(uint2*)(C + (size_t)(row + 8) * N + col) = v1;
            } else {
                float* C = (float*)Cv;
                float2 v0, v1;
                v0.x = acc[im][jn][0] + b0;
                v0.y = acc[im][jn][1] + b1;
                v1.x = acc[im][jn][2] + b0;
                v1.y = acc[im][jn][3] + b1;
                *(float2*)(C + (size_t)row * N + col)       = v0;
                *(float2*)(C + (size_t)(row + 8) * N + col) = v1;
            }
        }
    }
#endif
}

// ---------------------------------------------------------------------------
// Attention (causal), tcgen05 path — R15 structure (measured 282.7 total)
// with one trim: o*=alpha is folded into the post-PV accumulate as
// o = fma(o, alpha, O) — removes 64 FMUL issue slots per tile.
// TMEM: S 0-63/64-127 (pipelined), O 128-191, P 192-255 (TS mma).
// ---------------------------------------------------------------------------
#define AQ_OFF 256
#define AK_OFF (AQ_OFF + 8192)
#define AV_OFF (AK_OFF + 8192)
#define ATTN_SMEM ((AV_OFF + 8192) * 4)   // 99328 B
#define QPAD 68
#define VPAD 72

__global__ __launch_bounds__(128, 2)
void attn_tc(const unsigned* __restrict__ qkv, const unsigned* __restrict__ vt,
             unsigned* __restrict__ y)
{
    extern __shared__ unsigned smu[];
    const int qtile = (int)gridDim.x - 1 - (int)blockIdx.x;   // heavy first
    const int bh    = blockIdx.y;
    const int b = bh >> 4;
    const int h = bh & 15;
    const int tid  = threadIdx.x;
    const int warp = tid >> 5;
    const int lane = tid & 31;
    const int q0   = qtile * 128;
    const int ntiles = 2 * qtile + 2;

    const unsigned* qbase = qkv + (size_t)b * TSEQ * 3 * CDIM + h * HD;
    const unsigned* kbase = qbase + CDIM;

#if HAS_TCGEN05
    const uint32_t sbase  = (uint32_t)__cvta_generic_to_shared(smu);
    const uint32_t slot   = sbase;
    const uint32_t mbar_s = sbase + 16;
    const uint32_t mbar_o = sbase + 32;
    const unsigned* vtb = vt + (size_t)bh * HD * TSEQ;

    if (warp == 0) { TC_ALLOC(slot, 256); TC_RELINQ(); }
    if (tid == 0)  { MBAR_INIT(mbar_s, 1); MBAR_INIT(mbar_o, 1); }
    __syncthreads();
    uint32_t tmem;
    asm volatile("ld.shared.b32 %0, [%1];" : "=r"(tmem) : "r"(slot));

    auto fillkv = [&](int jt) {
        const int buf = jt & 1;
        const int j0  = jt * 64;
#pragma unroll
        for (int i = 0; i < 8; i++) {
            const int gi = tid + 128 * i;
            const int c  = gi >> 9;
            const int r  = (gi >> 3) & 63;
            const int qg = gi & 7;
            const uint32_t sw = (uint32_t)((qg ^ (r & 7)) << 4);
            cp_async16(sbase + (uint32_t)(AK_OFF + buf * 4096 + c * 2048 + r * 32) * 4u + sw,
                       kbase + (size_t)(j0 + r) * (3 * CDIM) + c * 32 + qg * 4);
            cp_async16(sbase + (uint32_t)(AV_OFF + buf * 4096 + c * 2048 + r * 32) * 4u + sw,
                       vtb + (size_t)r * TSEQ + j0 + c * 32 + qg * 4);
        }
    };

    auto issueS = [&](int jt) {
        const uint32_t dst = tmem + 64u * (uint32_t)(jt & 1);
#pragma unroll
        for (int c = 0; c < 2; c++) {
            const uint64_t ad = make_desc(sbase + (uint32_t)(AQ_OFF + c * 4096) * 4u);
            const uint64_t bd = make_desc(sbase + (uint32_t)(AK_OFF + (jt & 1) * 4096 + c * 2048) * 4u);
#pragma unroll
            for (int s = 0; s < 4; s++)
                tc_mma_tf32(dst, ad + 2 * s, bd + 2 * s, TC_IDESC_ATT,
                            (c > 0 || s > 0) ? 1u : 0u);
        }
        TC_COMMIT(mbar_s);
    };

#pragma unroll
    for (int i = 0; i < 16; i++) {
        const int gi = tid + 128 * i;
        const int c  = gi >> 10;
        const int r  = (gi >> 3) & 127;
        const int qg = gi & 7;
        const uint32_t sw = (uint32_t)((qg ^ (r & 7)) << 4);
        cp_async16(sbase + (uint32_t)(AQ_OFF + c * 4096 + r * 32) * 4u + sw,
                   qbase + (size_t)(q0 + r) * (3 * CDIM) + c * 32 + qg * 4);
    }
    fillkv(0);
    cp_commit();
    cp_wait<0>();
    __syncthreads();

    if (warp == 0 && elect_one()) {
        FENCE_PROXY();
        issueS(0);
    }

    float o[64];
#pragma unroll
    for (int i = 0; i < 64; i++) o[i] = 0.0f;
    float m_ = -1e30f, l_ = 0.0f;
    const float cs = 0.125f * 1.4426950408889634f;   // scale * log2(e)
    const int myrow = q0 + warp * 32 + lane;
    const uint32_t pdst = tmem + 192u + ((uint32_t)warp << 21);

    for (int jt = 0; jt < ntiles; jt++) {
        MBAR_WAIT(mbar_s, jt & 1);
        TC_FENCE_AFTER();

        if (jt + 1 < ntiles) { fillkv(jt + 1); cp_commit(); }

        unsigned su[64];
        const uint32_t sb_t = tmem + 64u * (uint32_t)(jt & 1);
        TC_LD_X32(su, sb_t);
        TC_LD_X32(su + 32, sb_t + 32);
        TC_WAIT_LD();
        TC_FENCE_BEFORE();

        const int j0 = jt * 64;
        const bool masked = (jt >= 2 * qtile);
        float mx = -1e30f;
#pragma unroll
        for (int i = 0; i < 64; i++) {
            float x = __uint_as_float(su[i]) * cs;
            if (masked && (j0 + i > myrow)) x = -1e30f;
            su[i] = __float_as_uint(x);
            mx = fmaxf(mx, x);
        }
        const float mnew  = fmaxf(m_, mx);
        const float alpha = exp2f(m_ - mnew);
        m_ = mnew;
        float rs = 0.0f;
#pragma unroll
        for (int i = 0; i < 64; i++) {
            const float p = exp2f(__uint_as_float(su[i]) - mnew);
            rs += p;
            su[i] = f2tf32(p);
        }
        l_ = l_ * alpha + rs;
        // NOTE: o *= alpha folded into the post-PV fma below.

        TC_ST_X32(pdst, su);
        TC_ST_X32(pdst + 32, su + 32);
        TC_WAIT_ST();
        TC_FENCE_BEFORE();

        if (jt + 1 < ntiles) cp_wait<0>();
        __syncthreads();

        if (warp == 0 && elect_one()) {
            TC_FENCE_AFTER();
#pragma unroll
            for (int c = 0; c < 2; c++) {
                const uint64_t bd = make_desc(sbase + (uint32_t)(AV_OFF + (jt & 1) * 4096 + c * 2048) * 4u);
#pragma unroll
                for (int s = 0; s < 4; s++) {
                    const uint32_t a_t = tmem + 192u + (uint32_t)((c * 4 + s) * 8);
                    tc_mma_tf32_ts(tmem + 128, a_t, bd + 2 * s, TC_IDESC_ATT,
                                   (c > 0 || s > 0) ? 1u : 0u);
                }
            }
            TC_COMMIT(mbar_o);
            if (jt + 1 < ntiles) issueS(jt + 1);
        }

        MBAR_WAIT(mbar_o, jt & 1);
        TC_FENCE_AFTER();

        unsigned ou[64];
        TC_LD_X32(ou, tmem + 128);
        TC_LD_X32(ou + 32, tmem + 160);
        TC_WAIT_LD();
        TC_FENCE_BEFORE();
#pragma unroll
        for (int i = 0; i < 64; i++)
            o[i] = fmaf(o[i], alpha, __uint_as_float(ou[i]));
    }

    const float inv = 1.0f / l_;
    unsigned* yrow = y + (size_t)(b * TSEQ + q0 + warp * 32 + lane) * CDIM + h * HD;
#pragma unroll
    for (int g16 = 0; g16 < 4; g16++) {
        const float* ob = o + g16 * 16;
        uint4 w0, w1, w2, w3;
        w0.x = f2tf32(ob[0]  * inv); w0.y = f2tf32(ob[4]  * inv);
        w0.z = f2tf32(ob[1]  * inv); w0.w = f2tf32(ob[5]  * inv);
        w1.x = f2tf32(ob[2]  * inv); w1.y = f2tf32(ob[6]  * inv);
        w1.z = f2tf32(ob[3]  * inv); w1.w = f2tf32(ob[7]  * inv);
        w2.x = f2tf32(ob[8]  * inv); w2.y = f2tf32(ob[12] * inv);
        w2.z = f2tf32(ob[9]  * inv); w2.w = f2tf32(ob[13] * inv);
        w3.x = f2tf32(ob[10] * inv); w3.y = f2tf32(ob[14] * inv);
        w3.z = f2tf32(ob[11] * inv); w3.w = f2tf32(ob[15] * inv);
        *(uint4*)(yrow + g16 * 16 + 0)  = w0;
        *(uint4*)(yrow + g16 * 16 + 4)  = w1;
        *(uint4*)(yrow + g16 * 16 + 8)  = w2;
        *(uint4*)(yrow + g16 * 16 + 12) = w3;
    }

    __syncthreads();
    if (warp == 0) TC_DEALLOC(tmem, 256);

#else
    // =============== HMMA fallback (compile-only on compute_103 pass) =======
    (void)vt;
    unsigned* Qs = smu;
    unsigned* Ps = Qs + 64 * QPAD;
    unsigned* Ks = Ps + 64 * QPAD;
    unsigned* Vs = Ks + 64 * QPAD;
    const unsigned* vbase = qbase + 2 * CDIM;

    const int g = lane >> 2;
    const int t = lane & 3;
    const int w16 = warp * 16;
    const int qq0 = qtile * 128;

    for (int idx = tid; idx < 64 * 16; idx += 128) {
        const int r  = idx >> 4;
        const int c4 = (idx & 15) * 4;
        *(uint4*)(Qs + r * QPAD + c4) =
            *(const uint4*)(qbase + (size_t)(qq0 + r) * (3 * CDIM) + c4);
    }

    float m_i[2], l_i[2], o[8][4];
#pragma unroll
    for (int rr = 0; rr < 2; rr++) { m_i[rr] = -1e30f; l_i[rr] = 0.0f; }
#pragma unroll
    for (int jn = 0; jn < 8; jn++)
#pragma unroll
        for (int c = 0; c < 4; c++) o[jn][c] = 0.0f;

    const float scale = 0.125f;

    for (int jt = 0; jt < ntiles; jt++) {
        const int j0 = jt * 64;
        __syncthreads();
        for (int idx = tid; idx < 64 * 16; idx += 128) {
            const int r  = idx >> 4;
            const int c4 = (idx & 15) * 4;
            *(uint4*)(Ks + r * QPAD + c4) =
                *(const uint4*)(kbase + (size_t)(j0 + r) * (3 * CDIM) + c4);
            *(uint4*)(Vs + r * QPAD + c4) =
                *(const uint4*)(vbase + (size_t)(j0 + r) * (3 * CDIM) + c4);
        }
        __syncthreads();

        float s[8][4];
#pragma unroll
        for (int jn = 0; jn < 8; jn++)
#pragma unroll
            for (int c = 0; c < 4; c++) s[jn][c] = 0.0f;

#pragma unroll
        for (int kc = 0; kc < 64; kc += 8) {
            unsigned a0 = Qs[(w16 + g    ) * QPAD + kc + t];
            unsigned a1 = Qs[(w16 + g + 8) * QPAD + kc + t];
            unsigned a2 = Qs[(w16 + g    ) * QPAD + kc + t + 4];
            unsigned a3 = Qs[(w16 + g + 8) * QPAD + kc + t + 4];
#pragma unroll
            for (int jn = 0; jn < 8; jn++) {
                unsigned b0 = Ks[(jn * 8 + g) * QPAD + kc + t];
                unsigned b1 = Ks[(jn * 8 + g) * QPAD + kc + t + 4];
                mma_tf32(s[jn], a0, a1, a2, a3, b0, b1);
            }
        }

#pragma unroll
        for (int rr = 0; rr < 2; rr++) {
            const int qrow = qq0 + w16 + g + 8 * rr;
            float mx = -1e30f;
#pragma unroll
            for (int jn = 0; jn < 8; jn++) {
                const int col = j0 + jn * 8 + 2 * t;
                float v0 = s[jn][2 * rr + 0] * scale;
                float v1 = s[jn][2 * rr + 1] * scale;
                v0 = (col     <= qrow) ? v0 : -1e30f;
                v1 = (col + 1 <= qrow) ? v1 : -1e30f;
                s[jn][2 * rr + 0] = v0;
                s[jn][2 * rr + 1] = v1;
                mx = fmaxf(mx, fmaxf(v0, v1));
            }
            mx = fmaxf(mx, __shfl_xor_sync(0xffffffffu, mx, 1));
            mx = fmaxf(mx, __shfl_xor_sync(0xffffffffu, mx, 2));
            const float mnew  = fmaxf(m_i[rr], mx);
            const float alpha = __expf(m_i[rr] - mnew);
            float rs = 0.0f;
            unsigned* prow = Ps + (w16 + g + 8 * rr) * QPAD;
#pragma unroll
            for (int jn = 0; jn < 8; jn++) {
                const float p0 = __expf(s[jn][2 * rr + 0] - mnew);
                const float p1 = __expf(s[jn][2 * rr + 1] - mnew);
                rs += p0 + p1;
                prow[jn * 8 + 2 * t    ] = f2tf32(p0);
                prow[jn * 8 + 2 * t + 1] = f2tf32(p1);
            }
            rs += __shfl_xor_sync(0xffffffffu, rs, 1);
            rs += __shfl_xor_sync(0xffffffffu, rs, 2);
            l_i[rr] = l_i[rr] * alpha + rs;
            m_i[rr] = mnew;
#pragma unroll
            for (int jn = 0; jn < 8; jn++) {
                o[jn][2 * rr + 0] *= alpha;
                o[jn][2 * rr + 1] *= alpha;
            }
        }
        __syncwarp();

#pragma unroll
        for (int kc = 0; kc < 64; kc += 8) {
            unsigned a0 = Ps[(w16 + g    ) * QPAD + kc + t];
            unsigned a1 = Ps[(w16 + g + 8) * QPAD + kc + t];
            unsigned a2 = Ps[(w16 + g    ) * QPAD + kc + t + 4];
            unsigned a3 = Ps[(w16 + g + 8) * QPAD + kc + t + 4];
#pragma unroll
            for (int jn = 0; jn < 8; jn++) {
                unsigned b0 = Vs[(kc + t    ) * QPAD + jn * 8 + g];
                unsigned b1 = Vs[(kc + t + 4) * QPAD + jn * 8 + g];
                mma_tf32(o[jn], a0, a1, a2, a3, b0, b1);
            }
        }
    }

    const float inv0 = 1.0f / l_i[0];
    const float inv1 = 1.0f / l_i[1];
    const int row0 = qq0 + w16 + g;
    unsigned* y0 = y + (size_t)b * TSEQ * CDIM + (size_t)row0 * CDIM;
    unsigned* y1 = y0 + 8 * CDIM;
#pragma unroll
    for (int jn = 0; jn < 8; jn++) {
        const int d  = h * HD + jn * 8 + 2 * t;
        const int p0 = (d & ~15) | perm16((d    ) & 15);
        const int p1 = (d & ~15) | perm16((d + 1) & 15);
        y0[p0] = f2tf32(o[jn][0] * inv0);
        y0[p1] = f2tf32(o[jn][1] * inv0);
        y1[p0] = f2tf32(o[jn][2] * inv1);
        y1[p1] = f2tf32(o[jn][3] * inv1);
    }
#endif
}

// ---------------------------------------------------------------------------
extern "C" void kernel_launch(void* const* d_in, const int* in_sizes, int n_in,
                              void* d_out, int out_size)
{
    (void)in_sizes; (void)n_in; (void)out_size;
    const float* x      = (const float*)d_in[0];
    const float* w_attn = (const float*)d_in[1];
    const float* b_attn = (const float*)d_in[2];
    const float* w_proj = (const float*)d_in[3];
    const float* b_proj = (const float*)d_in[4];
    float* out = (float*)d_out;

    unsigned *xt, *wat, *wpt, *qkv, *vtg, *yt;
    cudaGetSymbolAddress((void**)&xt,  g_xt);
    cudaGetSymbolAddress((void**)&wat, g_wat);
    cudaGetSymbolAddress((void**)&wpt, g_wpt);
    cudaGetSymbolAddress((void**)&qkv, g_qkv);
    cudaGetSymbolAddress((void**)&vtg, g_vt);
    cudaGetSymbolAddress((void**)&yt,  g_yt);

    cudaFuncSetAttribute(gemm_tc<true>,  cudaFuncAttributeMaxDynamicSharedMemorySize, GSMEM_TOTAL);
    cudaFuncSetAttribute(gemm_tc<false>, cudaFuncAttributeMaxDynamicSharedMemorySize, GSMEM_TOTAL);
    cudaFuncSetAttribute(attn_tc,        cudaFuncAttributeMaxDynamicSharedMemorySize, ATTN_SMEM);

    // 0) convert + permute all inputs to tf32 in ONE launch
    convert_all<<<CVT_BLOCKS, CVT_TPB>>>(x, w_attn, w_proj, xt, wat, wpt);

    // 1) QKV projection (128x256 tiles, R10 config) -> q,k + V^T
    gemm_tc<true><<<dim3(3 * CDIM / 256, MROWS / 128), 256, GSMEM_TOTAL>>>(
        xt, wat, b_attn, qkv, vtg, MROWS, 3 * CDIM, CDIM);

    // 2) causal flash attention (tcgen05, R15 structure + fma-fused rescale) -> y
    attn_tc<<<dim3(TSEQ / 128, BATCH * NHEAD), 128, ATTN_SMEM>>>(qkv, vtg, yt);

    // 3) output projection (128x256 tiles, R10 config) -> fp32
    gemm_tc<false><<<dim3(CDIM / 256, MROWS / 128), 256, GSMEM_TOTAL>>>(
        yt, wpt, b_proj, out, nullptr, MROWS, CDIM, CDIM);
}